// round 15
// baseline (speedup 1.0000x reference)
#include <cuda_runtime.h>
#include <cuda_fp16.h>
#include <cstdint>

#define BATCH   2048
#define IN_DIM  512
#define HID     1024
#define NEXP    16
#define EPSBN   1e-5f

// 3 stages x 32KB: A 128x64 fp16 (16KB) | B_e0 64x64 (8KB) | B_e1 64x64 (8KB)
// + epilogue params: sc 4K | sh 4K | gates 8K
#define STAGE_BYTES 32768
#define SM_SC  98304
#define SM_SH  102400
#define SM_G   106496
#define SMEM_TOTAL 114688

// ---------------- scratch (device globals) -----------------------------------
__device__ __align__(1024) __half g_xg[BATCH * IN_DIM];          // fp16
__device__ __align__(1024) __half g_W[NEXP * IN_DIM * HID];      // [e][k][n] fp16
__device__ float g_gate[BATCH * NEXP];
__device__ float g_scale[NEXP * HID];
__device__ float g_shift[NEXP * HID];

__device__ __forceinline__ int load_expert_idx(const void* p, int e) {
    const int* v = (const int*)p;
    bool is64 = ((v[1] | v[3] | v[5] | v[7]) == 0);
    return (is64 ? v[2 * e] : v[e]) & (NEXP - 1);
}

// ---------------- K1: ALL preps in one launch --------------------------------
// blocks [0, 2048)          : W gather+convert, 16 elems/thread
// blocks [2048, 2048+256)   : LoRA+softmax gate, 8 rows/block (warp-per-row)
// blocks [2304, 2304+64)    : BN scale/shift fold
#define PW_BLOCKS 2048
#define XG_BLOCKS 256
#define PP_BLOCKS 64

__global__ void __launch_bounds__(256) prep_all(
    const float* __restrict__ x, const float* __restrict__ gs_in,
    const float* __restrict__ gate_w, const float* __restrict__ lora_A,
    const float* __restrict__ lora_B,
    const void* __restrict__ eidx, const float* __restrict__ ew,
    const float* __restrict__ eb,
    const float* __restrict__ bnw, const float* __restrict__ bnb,
    const float* __restrict__ rm, const float* __restrict__ rv)
{
    const int bid = blockIdx.x;

    if (bid < PW_BLOCKS) {
        // ---- W gather + fp16 convert, 16 elems/thread ----
        int i  = (bid * 256 + threadIdx.x) * 16;
        int e  = i >> 19;
        int rem = i & ((1 << 19) - 1);
        int se = load_expert_idx(eidx, e);
        const float4* src = (const float4*)(ew + (size_t)se * (IN_DIM * HID) + rem);
#pragma unroll
        for (int h = 0; h < 2; h++) {
            float4 a = src[h * 2], b = src[h * 2 + 1];
            __half hv[8] = {
                __float2half_rn(a.x), __float2half_rn(a.y),
                __float2half_rn(a.z), __float2half_rn(a.w),
                __float2half_rn(b.x), __float2half_rn(b.y),
                __float2half_rn(b.z), __float2half_rn(b.w) };
            *(uint4*)(g_W + i + h * 8) = *(uint4*)hv;
        }
        return;
    }

    if (bid < PW_BLOCKS + XG_BLOCKS) {
        // ---- LoRA sigmoid gate + softmax gate: warp-per-row, 8 rows/block ----
        const int lane = threadIdx.x & 31, wid = threadIdx.x >> 5;
        const int row = (bid - PW_BLOCKS) * 8 + wid;

        const float* xr = x     + (size_t)row * IN_DIM;
        const float* gr = gs_in + (size_t)row * IN_DIM;

        float xv[16], gv[16];
#pragma unroll
        for (int j = 0; j < 16; j++) {
            xv[j] = xr[lane + 32 * j];
            gv[j] = gr[lane + 32 * j];
        }

        float p0 = 0.f, p1 = 0.f;
#pragma unroll
        for (int j = 0; j < 16; j++) {
            int i = lane + 32 * j;
            float2 a = *(const float2*)(lora_A + 2 * i);
            p0 = fmaf(xv[j], a.x, p0);
            p1 = fmaf(xv[j], a.y, p1);
        }
#pragma unroll
        for (int o = 16; o > 0; o >>= 1) {
            p0 += __shfl_xor_sync(~0u, p0, o);
            p1 += __shfl_xor_sync(~0u, p1, o);
        }

        float pe[16];
#pragma unroll
        for (int e = 0; e < 16; e++) pe[e] = 0.f;
#pragma unroll
        for (int j = 0; j < 16; j++) {
            int i = lane + 32 * j;
            const float4* gwv = (const float4*)(gate_w + (size_t)i * 16);
            float4 w0 = gwv[0], w1 = gwv[1], w2 = gwv[2], w3 = gwv[3];
            float v = gv[j];
            pe[0]  = fmaf(v, w0.x, pe[0]);  pe[1]  = fmaf(v, w0.y, pe[1]);
            pe[2]  = fmaf(v, w0.z, pe[2]);  pe[3]  = fmaf(v, w0.w, pe[3]);
            pe[4]  = fmaf(v, w1.x, pe[4]);  pe[5]  = fmaf(v, w1.y, pe[5]);
            pe[6]  = fmaf(v, w1.z, pe[6]);  pe[7]  = fmaf(v, w1.w, pe[7]);
            pe[8]  = fmaf(v, w2.x, pe[8]);  pe[9]  = fmaf(v, w2.y, pe[9]);
            pe[10] = fmaf(v, w2.z, pe[10]); pe[11] = fmaf(v, w2.w, pe[11]);
            pe[12] = fmaf(v, w3.x, pe[12]); pe[13] = fmaf(v, w3.y, pe[13]);
            pe[14] = fmaf(v, w3.z, pe[14]); pe[15] = fmaf(v, w3.w, pe[15]);
        }
#pragma unroll
        for (int o = 16; o > 0; o >>= 1)
#pragma unroll
            for (int e = 0; e < 16; e++)
                pe[e] += __shfl_xor_sync(~0u, pe[e], o);

        float m = pe[0];
#pragma unroll
        for (int e = 1; e < 16; e++) m = fmaxf(m, pe[e]);
        float ex[16], s = 0.f;
#pragma unroll
        for (int e = 0; e < 16; e++) { ex[e] = __expf(pe[e] - m); s += ex[e]; }
        float inv = __fdividef(1.f, s);
        if (lane < 16) {
            float g = 0.f;
#pragma unroll
            for (int e = 0; e < 16; e++) if (lane == e) g = ex[e];
            g_gate[row * 16 + lane] = g * inv;
        }

#pragma unroll
        for (int j = 0; j < 16; j++) {
            int i = lane + 32 * j;
            float z = fmaf(p0, lora_B[i], p1 * lora_B[IN_DIM + i]);
            float v = xv[j] * __fdividef(1.f, 1.f + __expf(-z));
            g_xg[(size_t)row * IN_DIM + i] = __float2half_rn(v);
        }
        return;
    }

    // ---- BN scale/shift fold ----
    {
        int i = (bid - PW_BLOCKS - XG_BLOCKS) * 256 + threadIdx.x;   // < 16384
        int e = i >> 10;
        int se = load_expert_idx(eidx, e);
        size_t s = (size_t)se * HID + (i & 1023);
        float inv = rsqrtf(rv[s] + EPSBN);
        float sc  = bnw[s] * inv;
        float sh  = fmaf(-rm[s], sc, bnb[s]);
        g_scale[i] = sc;
        g_shift[i] = fmaf(eb[s], sc, sh);
    }
}

// ---------------- K3: fused fp16 GEMM — 3-stage ring, ldsm-first order ------
#define SWZ(o) ((o) ^ (((o) >> 3) & 0x70))   /* 128B rows (A and B tiles) */

__device__ __forceinline__ uint32_t smem_u32(const void* p) {
    return (uint32_t)__cvta_generic_to_shared(p);
}
__device__ __forceinline__ void ldsm_x4(uint32_t* r, uint32_t a) {
    asm volatile("ldmatrix.sync.aligned.m8n8.x4.shared.b16 {%0,%1,%2,%3}, [%4];"
                 : "=r"(r[0]), "=r"(r[1]), "=r"(r[2]), "=r"(r[3]) : "r"(a));
}
__device__ __forceinline__ void ldsm_x4_t(uint32_t* r, uint32_t a) {
    asm volatile("ldmatrix.sync.aligned.m8n8.x4.trans.shared.b16 {%0,%1,%2,%3}, [%4];"
                 : "=r"(r[0]), "=r"(r[1]), "=r"(r[2]), "=r"(r[3]) : "r"(a));
}
__device__ __forceinline__ void mma16816(float* c, const uint32_t* a, const uint32_t* b) {
    asm volatile(
        "mma.sync.aligned.m16n8k16.row.col.f32.f16.f16.f32 "
        "{%0,%1,%2,%3}, {%4,%5,%6,%7}, {%8,%9}, {%0,%1,%2,%3};"
        : "+f"(c[0]), "+f"(c[1]), "+f"(c[2]), "+f"(c[3])
        : "r"(a[0]), "r"(a[1]), "r"(a[2]), "r"(a[3]), "r"(b[0]), "r"(b[1]));
}
#define CP16(d, s)  asm volatile("cp.async.cg.shared.global [%0], [%1], 16;" :: "r"(d), "l"(s) : "memory")
#define CP_COMMIT() asm volatile("cp.async.commit_group;" ::: "memory")
#define CP_WAIT1()  asm volatile("cp.async.wait_group 1;" ::: "memory")
#define CP_WAIT0()  asm volatile("cp.async.wait_group 0;" ::: "memory")

// flat iteration t: ep = t>>3 (expert pair), kc = t&7 (K64 chunk)
__device__ __forceinline__ void load_stage(uint32_t base, int bblk, int hblk,
                                           int t, int tid)
{
    const int ep = t >> 3, kc = t & 7;
    const int e0 = ep * 2;
    // A: 128 rows x 64 k fp16 = 128B rows (16KB)
#pragma unroll
    for (int j = 0; j < 4; j++) {
        int idx = j * 256 + tid;                 // 0..1023
        int r = idx >> 3, c = idx & 7;
        const __half* s = g_xg + (size_t)(bblk * 128 + r) * IN_DIM + kc * 64 + c * 8;
        CP16(base + SWZ(r * 128 + c * 16), s);
    }
    // B for e0, e1: 64 k-rows x 64 n = 128B rows (8KB each)
#pragma unroll
    for (int j = 0; j < 2; j++) {
        int idx = j * 256 + tid;                 // 0..511
        int r = idx >> 3, c = idx & 7;
        uint32_t d = SWZ(r * 128 + c * 16);
        const __half* s0 = g_W + ((size_t)e0 * IN_DIM + kc * 64 + r) * HID + hblk * 64 + c * 8;
        CP16(base + 16384 + d, s0);
        CP16(base + 24576 + d, s0 + (size_t)IN_DIM * HID);   // e1 = e0+1
    }
    CP_COMMIT();
}

__global__ void __launch_bounds__(256, 2) fused_moe(float* __restrict__ out)
{
    extern __shared__ __align__(1024) char smem[];
    const uint32_t sb = smem_u32(smem);
    float* sSc = (float*)(smem + SM_SC);   // [16 e][64 col]
    float* sSh = (float*)(smem + SM_SH);
    float* sG  = (float*)(smem + SM_G);    // [128 row][16 e]

    const int tid  = threadIdx.x;
    const int lane = tid & 31, wid = tid >> 5;
    const int hblk = blockIdx.x, bblk = blockIdx.y;
    const int wm = wid >> 1, wn = wid & 1;
    const int m0 = wm * 32,  n0 = wn * 32;
    const int i8 = lane & 7, g8 = lane >> 3;
    const int tig = lane & 3, grp = lane >> 2;

    float o[2][4][4];
#pragma unroll
    for (int a = 0; a < 2; a++)
#pragma unroll
        for (int b = 0; b < 4; b++)
#pragma unroll
            for (int d = 0; d < 4; d++) o[a][b][d] = 0.f;

    float c[2][2][4][4];                  // [expert-in-pair][mt][ng][d]
#pragma unroll
    for (int p = 0; p < 2; p++)
#pragma unroll
        for (int a = 0; a < 2; a++)
#pragma unroll
            for (int b = 0; b < 4; b++)
#pragma unroll
                for (int d = 0; d < 4; d++) c[p][a][b][d] = 0.f;

    // prologue: stages 0 and 1
    load_stage(sb,               bblk, hblk, 0, tid);
    load_stage(sb + STAGE_BYTES, bblk, hblk, 1, tid);

    // preload epilogue params into smem (first reads come after first barrier)
#pragma unroll
    for (int j = 0; j < 4; j++) {
        int idx = j * 256 + tid;
        sSc[idx] = g_scale[(idx >> 6) * HID + hblk * 64 + (idx & 63)];
        sSh[idx] = g_shift[(idx >> 6) * HID + hblk * 64 + (idx & 63)];
    }
#pragma unroll
    for (int j = 0; j < 8; j++) {
        int idx = j * 256 + tid;
        sG[idx] = g_gate[(bblk * 128 + (idx >> 4)) * 16 + (idx & 15)];
    }

    for (int t = 0; t < 64; t++) {               // ep = t>>3, kc = t&7
        if (t < 63) CP_WAIT1(); else CP_WAIT0(); // group t complete; t+1 in flight
        __syncthreads();                         // t visible; all readers of t-1 done

        const uint32_t uA  = sb + (t % 3) * STAGE_BYTES;
        const uint32_t uB0 = uA + 16384;
        const uint32_t uB1 = uA + 24576;

        // ---- compute t FIRST: all 6 LDSM per ks up-front (no b WAR), then MMAs
#pragma unroll
        for (int ks = 0; ks < 4; ks++) {
            const int k0 = ks * 16;
            uint32_t a[2][4], b0[4][2], b1[4][2];
#pragma unroll
            for (int mt = 0; mt < 2; mt++) {
                int row = m0 + mt * 16 + i8 + ((g8 & 1) << 3);
                int col = k0 + ((g8 >> 1) << 3);
                ldsm_x4(a[mt], uA + SWZ(row * 128 + col * 2));
            }
#pragma unroll
            for (int q = 0; q < 2; q++) {
                int row = k0 + ((g8 & 1) << 3) + i8;
                int col = n0 + q * 16 + ((g8 >> 1) << 3);
                uint32_t d = SWZ(row * 128 + col * 2);
                uint32_t t0[4], t1[4];
                ldsm_x4_t(t0, uB0 + d);
                ldsm_x4_t(t1, uB1 + d);
                b0[q * 2][0]     = t0[0]; b0[q * 2][1]     = t0[1];
                b0[q * 2 + 1][0] = t0[2]; b0[q * 2 + 1][1] = t0[3];
                b1[q * 2][0]     = t1[0]; b1[q * 2][1]     = t1[1];
                b1[q * 2 + 1][0] = t1[2]; b1[q * 2 + 1][1] = t1[3];
            }
#pragma unroll
            for (int mt = 0; mt < 2; mt++)
#pragma unroll
                for (int ng = 0; ng < 4; ng++)
                    mma16816(c[0][mt][ng], a[mt], b0[ng]);
#pragma unroll
            for (int mt = 0; mt < 2; mt++)
#pragma unroll
                for (int ng = 0; ng < 4; ng++)
                    mma16816(c[1][mt][ng], a[mt], b1[ng]);
        }

        // ---- per-expert-pair epilogue ----
        if ((t & 7) == 7) {
            const int ep = t >> 3;
#pragma unroll
            for (int p = 0; p < 2; p++) {
                const int e = ep * 2 + p;
                const float* scp = sSc + e * 64;
                const float* shp = sSh + e * 64;
#pragma unroll
                for (int mt = 0; mt < 2; mt++) {
                    int rl = m0 + mt * 16 + grp;
                    float gw0 = sG[rl * 16 + e];
                    float gw1 = sG[(rl + 8) * 16 + e];
#pragma unroll
                    for (int ng = 0; ng < 4; ng++) {
                        int hl = n0 + ng * 8 + tig * 2;
                        float sc0 = scp[hl], sc1 = scp[hl + 1];
                        float sh0 = shp[hl], sh1 = shp[hl + 1];
                        float z;
                        z = fmaf(c[p][mt][ng][0], sc0, sh0);
                        o[mt][ng][0] = fmaf(gw0, __fdividef(z, 1.f + __expf(-z)), o[mt][ng][0]);
                        z = fmaf(c[p][mt][ng][1], sc1, sh1);
                        o[mt][ng][1] = fmaf(gw0, __fdividef(z, 1.f + __expf(-z)), o[mt][ng][1]);
                        z = fmaf(c[p][mt][ng][2], sc0, sh0);
                        o[mt][ng][2] = fmaf(gw1, __fdividef(z, 1.f + __expf(-z)), o[mt][ng][2]);
                        z = fmaf(c[p][mt][ng][3], sc1, sh1);
                        o[mt][ng][3] = fmaf(gw1, __fdividef(z, 1.f + __expf(-z)), o[mt][ng][3]);
                        c[p][mt][ng][0] = 0.f; c[p][mt][ng][1] = 0.f;
                        c[p][mt][ng][2] = 0.f; c[p][mt][ng][3] = 0.f;
                    }
                }
            }
        }

        // ---- issue loads for t+2 LAST (into buf[(t+2)%3] = buf[(t-1)%3]) ----
        if (t + 2 < 64)
            load_stage(sb + ((t + 2) % 3) * STAGE_BYTES, bblk, hblk, t + 2, tid);
    }

    // -------- store combined output --------
#pragma unroll
    for (int mt = 0; mt < 2; mt++) {
        int b0r = bblk * 128 + m0 + mt * 16 + grp;
#pragma unroll
        for (int ng = 0; ng < 4; ng++) {
            int h = hblk * 64 + n0 + ng * 8 + tig * 2;
            *(float2*)(out + (size_t)b0r * HID + h)       = make_float2(o[mt][ng][0], o[mt][ng][1]);
            *(float2*)(out + (size_t)(b0r + 8) * HID + h) = make_float2(o[mt][ng][2], o[mt][ng][3]);
        }
    }
}

// ---------------- launch ------------------------------------------------------
extern "C" void kernel_launch(void* const* d_in, const int* in_sizes, int n_in,
                              void* d_out, int out_size)
{
    const float* x   = (const float*)d_in[0];
    const float* gs  = (const float*)d_in[1];
    const void*  ei  = d_in[2];
    const float* ew  = (const float*)d_in[3];
    const float* eb  = (const float*)d_in[4];
    const float* bnw = (const float*)d_in[5];
    const float* bnb = (const float*)d_in[6];
    const float* rm  = (const float*)d_in[7];
    const float* rv  = (const float*)d_in[8];
    const float* gw  = (const float*)d_in[9];
    const float* lA  = (const float*)d_in[10];
    const float* lB  = (const float*)d_in[11];
    float* out = (float*)d_out;

    cudaFuncSetAttribute(fused_moe, cudaFuncAttributeMaxDynamicSharedMemorySize, SMEM_TOTAL);

    prep_all<<<PW_BLOCKS + XG_BLOCKS + PP_BLOCKS, 256>>>(
        x, gs, gw, lA, lB, ei, ew, eb, bnw, bnb, rm, rv);
    fused_moe<<<dim3(HID / 64, BATCH / 128), 256, SMEM_TOTAL>>>(out);
}

// round 16
// speedup vs baseline: 1.0288x; 1.0288x over previous
#include <cuda_runtime.h>
#include <cuda_fp16.h>
#include <cstdint>

#define BATCH   2048
#define IN_DIM  512
#define HID     1024
#define NEXP    16
#define EPSBN   1e-5f

// 3 stages x 32KB: A 128x64 fp16 (16KB) | B_e0 64x64 (8KB) | B_e1 64x64 (8KB)
// + epilogue params: sc 4K | sh 4K | gates 8K
#define STAGE_BYTES 32768
#define SM_SC  98304
#define SM_SH  102400
#define SM_G   106496
#define SMEM_TOTAL 114688

// ---------------- scratch (device globals) -----------------------------------
__device__ __align__(1024) __half g_xg[BATCH * IN_DIM];          // fp16
__device__ __align__(1024) __half g_W[NEXP * IN_DIM * HID];      // [e][k][n] fp16
__device__ float g_gate[BATCH * NEXP];
__device__ float g_scale[NEXP * HID];
__device__ float g_shift[NEXP * HID];

__device__ __forceinline__ int load_expert_idx(const void* p, int e) {
    const int* v = (const int*)p;
    bool is64 = ((v[1] | v[3] | v[5] | v[7]) == 0);
    return (is64 ? v[2 * e] : v[e]) & (NEXP - 1);
}

// ---------------- K1: gather W -> fp16, 16 elems/thread ---------------------
__global__ void __launch_bounds__(256) prep_W(
    const void* __restrict__ eidx, const float* __restrict__ ew)
{
    int i   = (blockIdx.x * 256 + threadIdx.x) * 16;
    int e   = i >> 19;
    int rem = i & ((1 << 19) - 1);
    int se  = load_expert_idx(eidx, e);
    const float4* src = (const float4*)(ew + (size_t)se * (IN_DIM * HID) + rem);
#pragma unroll
    for (int h = 0; h < 2; h++) {
        float4 a = src[h * 2], b = src[h * 2 + 1];
        __half hv[8] = {
            __float2half_rn(a.x), __float2half_rn(a.y),
            __float2half_rn(a.z), __float2half_rn(a.w),
            __float2half_rn(b.x), __float2half_rn(b.y),
            __float2half_rn(b.z), __float2half_rn(b.w) };
        *(uint4*)(g_W + i + h * 8) = *(uint4*)hv;
    }
}

// ---------------- K2: LoRA+softmax gate AND BN params in one launch ---------
// blocks [0,256): warp-per-row xg gate (8 rows/block of 256 thr)
// blocks [256,320): BN scale/shift fold (16384 elems)
__global__ void __launch_bounds__(256) prep_small(
    const float* __restrict__ x, const float* __restrict__ gs_in,
    const float* __restrict__ gate_w, const float* __restrict__ lora_A,
    const float* __restrict__ lora_B,
    const void* __restrict__ eidx, const float* __restrict__ eb,
    const float* __restrict__ bnw, const float* __restrict__ bnb,
    const float* __restrict__ rm, const float* __restrict__ rv)
{
    const int bid = blockIdx.x;
    if (bid >= 256) {
        int i = (bid - 256) * 256 + threadIdx.x;     // < 16384
        int e = i >> 10;
        int se = load_expert_idx(eidx, e);
        size_t s = (size_t)se * HID + (i & 1023);
        float inv = rsqrtf(rv[s] + EPSBN);
        float sc  = bnw[s] * inv;
        float sh  = fmaf(-rm[s], sc, bnb[s]);
        g_scale[i] = sc;
        g_shift[i] = fmaf(eb[s], sc, sh);
        return;
    }

    const int lane = threadIdx.x & 31, wid = threadIdx.x >> 5;
    const int row = bid * 8 + wid;

    const float* xr = x     + (size_t)row * IN_DIM;
    const float* gr = gs_in + (size_t)row * IN_DIM;

    float xv[16], gv[16];
#pragma unroll
    for (int j = 0; j < 16; j++) {
        xv[j] = xr[lane + 32 * j];
        gv[j] = gr[lane + 32 * j];
    }

    float p0 = 0.f, p1 = 0.f;
#pragma unroll
    for (int j = 0; j < 16; j++) {
        int i = lane + 32 * j;
        float2 a = *(const float2*)(lora_A + 2 * i);
        p0 = fmaf(xv[j], a.x, p0);
        p1 = fmaf(xv[j], a.y, p1);
    }
#pragma unroll
    for (int o = 16; o > 0; o >>= 1) {
        p0 += __shfl_xor_sync(~0u, p0, o);
        p1 += __shfl_xor_sync(~0u, p1, o);
    }

    float pe[16];
#pragma unroll
    for (int e = 0; e < 16; e++) pe[e] = 0.f;
#pragma unroll
    for (int j = 0; j < 16; j++) {
        int i = lane + 32 * j;
        const float4* gwv = (const float4*)(gate_w + (size_t)i * 16);
        float4 w0 = gwv[0], w1 = gwv[1], w2 = gwv[2], w3 = gwv[3];
        float v = gv[j];
        pe[0]  = fmaf(v, w0.x, pe[0]);  pe[1]  = fmaf(v, w0.y, pe[1]);
        pe[2]  = fmaf(v, w0.z, pe[2]);  pe[3]  = fmaf(v, w0.w, pe[3]);
        pe[4]  = fmaf(v, w1.x, pe[4]);  pe[5]  = fmaf(v, w1.y, pe[5]);
        pe[6]  = fmaf(v, w1.z, pe[6]);  pe[7]  = fmaf(v, w1.w, pe[7]);
        pe[8]  = fmaf(v, w2.x, pe[8]);  pe[9]  = fmaf(v, w2.y, pe[9]);
        pe[10] = fmaf(v, w2.z, pe[10]); pe[11] = fmaf(v, w2.w, pe[11]);
        pe[12] = fmaf(v, w3.x, pe[12]); pe[13] = fmaf(v, w3.y, pe[13]);
        pe[14] = fmaf(v, w3.z, pe[14]); pe[15] = fmaf(v, w3.w, pe[15]);
    }
#pragma unroll
    for (int o = 16; o > 0; o >>= 1)
#pragma unroll
        for (int e = 0; e < 16; e++)
            pe[e] += __shfl_xor_sync(~0u, pe[e], o);

    float m = pe[0];
#pragma unroll
    for (int e = 1; e < 16; e++) m = fmaxf(m, pe[e]);
    float ex[16], s = 0.f;
#pragma unroll
    for (int e = 0; e < 16; e++) { ex[e] = __expf(pe[e] - m); s += ex[e]; }
    float inv = __fdividef(1.f, s);
    if (lane < 16) {
        float g = 0.f;
#pragma unroll
        for (int e = 0; e < 16; e++) if (lane == e) g = ex[e];
        g_gate[row * 16 + lane] = g * inv;
    }

#pragma unroll
    for (int j = 0; j < 16; j++) {
        int i = lane + 32 * j;
        float z = fmaf(p0, lora_B[i], p1 * lora_B[IN_DIM + i]);
        float v = xv[j] * __fdividef(1.f, 1.f + __expf(-z));
        g_xg[(size_t)row * IN_DIM + i] = __float2half_rn(v);
    }
}

// ---------------- K3: fused fp16 GEMM — 3-stage ring, ldsm-first order ------
#define SWZ(o) ((o) ^ (((o) >> 3) & 0x70))   /* 128B rows (A and B tiles) */

__device__ __forceinline__ uint32_t smem_u32(const void* p) {
    return (uint32_t)__cvta_generic_to_shared(p);
}
__device__ __forceinline__ void ldsm_x4(uint32_t* r, uint32_t a) {
    asm volatile("ldmatrix.sync.aligned.m8n8.x4.shared.b16 {%0,%1,%2,%3}, [%4];"
                 : "=r"(r[0]), "=r"(r[1]), "=r"(r[2]), "=r"(r[3]) : "r"(a));
}
__device__ __forceinline__ void ldsm_x4_t(uint32_t* r, uint32_t a) {
    asm volatile("ldmatrix.sync.aligned.m8n8.x4.trans.shared.b16 {%0,%1,%2,%3}, [%4];"
                 : "=r"(r[0]), "=r"(r[1]), "=r"(r[2]), "=r"(r[3]) : "r"(a));
}
__device__ __forceinline__ void mma16816(float* c, const uint32_t* a, const uint32_t* b) {
    asm volatile(
        "mma.sync.aligned.m16n8k16.row.col.f32.f16.f16.f32 "
        "{%0,%1,%2,%3}, {%4,%5,%6,%7}, {%8,%9}, {%0,%1,%2,%3};"
        : "+f"(c[0]), "+f"(c[1]), "+f"(c[2]), "+f"(c[3])
        : "r"(a[0]), "r"(a[1]), "r"(a[2]), "r"(a[3]), "r"(b[0]), "r"(b[1]));
}
#define CP16(d, s)  asm volatile("cp.async.cg.shared.global [%0], [%1], 16;" :: "r"(d), "l"(s) : "memory")
#define CP_COMMIT() asm volatile("cp.async.commit_group;" ::: "memory")
#define CP_WAIT1()  asm volatile("cp.async.wait_group 1;" ::: "memory")
#define CP_WAIT0()  asm volatile("cp.async.wait_group 0;" ::: "memory")

// flat iteration t: ep = t>>3 (expert pair), kc = t&7 (K64 chunk)
__device__ __forceinline__ void load_stage(uint32_t base, int bblk, int hblk,
                                           int t, int tid)
{
    const int ep = t >> 3, kc = t & 7;
    const int e0 = ep * 2;
    // A: 128 rows x 64 k fp16 = 128B rows (16KB)
#pragma unroll
    for (int j = 0; j < 4; j++) {
        int idx = j * 256 + tid;                 // 0..1023
        int r = idx >> 3, c = idx & 7;
        const __half* s = g_xg + (size_t)(bblk * 128 + r) * IN_DIM + kc * 64 + c * 8;
        CP16(base + SWZ(r * 128 + c * 16), s);
    }
    // B for e0, e1: 64 k-rows x 64 n = 128B rows (8KB each)
#pragma unroll
    for (int j = 0; j < 2; j++) {
        int idx = j * 256 + tid;                 // 0..511
        int r = idx >> 3, c = idx & 7;
        uint32_t d = SWZ(r * 128 + c * 16);
        const __half* s0 = g_W + ((size_t)e0 * IN_DIM + kc * 64 + r) * HID + hblk * 64 + c * 8;
        CP16(base + 16384 + d, s0);
        CP16(base + 24576 + d, s0 + (size_t)IN_DIM * HID);   // e1 = e0+1
    }
    CP_COMMIT();
}

__global__ void __launch_bounds__(256, 2) fused_moe(float* __restrict__ out)
{
    extern __shared__ __align__(1024) char smem[];
    const uint32_t sb = smem_u32(smem);
    float* sSc = (float*)(smem + SM_SC);   // [16 e][64 col]
    float* sSh = (float*)(smem + SM_SH);
    float* sG  = (float*)(smem + SM_G);    // [128 row][16 e]

    const int tid  = threadIdx.x;
    const int lane = tid & 31, wid = tid >> 5;
    const int hblk = blockIdx.x, bblk = blockIdx.y;
    const int wm = wid >> 1, wn = wid & 1;
    const int m0 = wm * 32,  n0 = wn * 32;
    const int i8 = lane & 7, g8 = lane >> 3;
    const int tig = lane & 3, grp = lane >> 2;

    float o[2][4][4];
#pragma unroll
    for (int a = 0; a < 2; a++)
#pragma unroll
        for (int b = 0; b < 4; b++)
#pragma unroll
            for (int d = 0; d < 4; d++) o[a][b][d] = 0.f;

    float c[2][2][4][4];                  // [expert-in-pair][mt][ng][d]
#pragma unroll
    for (int p = 0; p < 2; p++)
#pragma unroll
        for (int a = 0; a < 2; a++)
#pragma unroll
            for (int b = 0; b < 4; b++)
#pragma unroll
                for (int d = 0; d < 4; d++) c[p][a][b][d] = 0.f;

    // prologue: stages 0 and 1
    load_stage(sb,               bblk, hblk, 0, tid);
    load_stage(sb + STAGE_BYTES, bblk, hblk, 1, tid);

    // preload epilogue params into smem (first reads come after first barrier)
#pragma unroll
    for (int j = 0; j < 4; j++) {
        int idx = j * 256 + tid;
        sSc[idx] = g_scale[(idx >> 6) * HID + hblk * 64 + (idx & 63)];
        sSh[idx] = g_shift[(idx >> 6) * HID + hblk * 64 + (idx & 63)];
    }
#pragma unroll
    for (int j = 0; j < 8; j++) {
        int idx = j * 256 + tid;
        sG[idx] = g_gate[(bblk * 128 + (idx >> 4)) * 16 + (idx & 15)];
    }

    for (int t = 0; t < 64; t++) {               // ep = t>>3, kc = t&7
        if (t < 63) CP_WAIT1(); else CP_WAIT0(); // group t complete; t+1 in flight
        __syncthreads();                         // t visible; all readers of t-1 done

        const uint32_t uA  = sb + (t % 3) * STAGE_BYTES;
        const uint32_t uB0 = uA + 16384;
        const uint32_t uB1 = uA + 24576;

        // ---- compute t FIRST: all 6 LDSM per ks up-front, then MMAs ----
#pragma unroll
        for (int ks = 0; ks < 4; ks++) {
            const int k0 = ks * 16;
            uint32_t a[2][4], b0[4][2], b1[4][2];
#pragma unroll
            for (int mt = 0; mt < 2; mt++) {
                int row = m0 + mt * 16 + i8 + ((g8 & 1) << 3);
                int col = k0 + ((g8 >> 1) << 3);
                ldsm_x4(a[mt], uA + SWZ(row * 128 + col * 2));
            }
#pragma unroll
            for (int q = 0; q < 2; q++) {
                int row = k0 + ((g8 & 1) << 3) + i8;
                int col = n0 + q * 16 + ((g8 >> 1) << 3);
                uint32_t d = SWZ(row * 128 + col * 2);
                uint32_t t0[4], t1[4];
                ldsm_x4_t(t0, uB0 + d);
                ldsm_x4_t(t1, uB1 + d);
                b0[q * 2][0]     = t0[0]; b0[q * 2][1]     = t0[1];
                b0[q * 2 + 1][0] = t0[2]; b0[q * 2 + 1][1] = t0[3];
                b1[q * 2][0]     = t1[0]; b1[q * 2][1]     = t1[1];
                b1[q * 2 + 1][0] = t1[2]; b1[q * 2 + 1][1] = t1[3];
            }
#pragma unroll
            for (int mt = 0; mt < 2; mt++)
#pragma unroll
                for (int ng = 0; ng < 4; ng++)
                    mma16816(c[0][mt][ng], a[mt], b0[ng]);
#pragma unroll
            for (int mt = 0; mt < 2; mt++)
#pragma unroll
                for (int ng = 0; ng < 4; ng++)
                    mma16816(c[1][mt][ng], a[mt], b1[ng]);
        }

        // ---- per-expert-pair epilogue ----
        if ((t & 7) == 7) {
            const int ep = t >> 3;
#pragma unroll
            for (int p = 0; p < 2; p++) {
                const int e = ep * 2 + p;
                const float* scp = sSc + e * 64;
                const float* shp = sSh + e * 64;
#pragma unroll
                for (int mt = 0; mt < 2; mt++) {
                    int rl = m0 + mt * 16 + grp;
                    float gw0 = sG[rl * 16 + e];
                    float gw1 = sG[(rl + 8) * 16 + e];
#pragma unroll
                    for (int ng = 0; ng < 4; ng++) {
                        int hl = n0 + ng * 8 + tig * 2;
                        float sc0 = scp[hl], sc1 = scp[hl + 1];
                        float sh0 = shp[hl], sh1 = shp[hl + 1];
                        float z;
                        z = fmaf(c[p][mt][ng][0], sc0, sh0);
                        o[mt][ng][0] = fmaf(gw0, __fdividef(z, 1.f + __expf(-z)), o[mt][ng][0]);
                        z = fmaf(c[p][mt][ng][1], sc1, sh1);
                        o[mt][ng][1] = fmaf(gw0, __fdividef(z, 1.f + __expf(-z)), o[mt][ng][1]);
                        z = fmaf(c[p][mt][ng][2], sc0, sh0);
                        o[mt][ng][2] = fmaf(gw1, __fdividef(z, 1.f + __expf(-z)), o[mt][ng][2]);
                        z = fmaf(c[p][mt][ng][3], sc1, sh1);
                        o[mt][ng][3] = fmaf(gw1, __fdividef(z, 1.f + __expf(-z)), o[mt][ng][3]);
                        c[p][mt][ng][0] = 0.f; c[p][mt][ng][1] = 0.f;
                        c[p][mt][ng][2] = 0.f; c[p][mt][ng][3] = 0.f;
                    }
                }
            }
        }

        // ---- issue loads for t+2 LAST (into buf[(t+2)%3] = buf[(t-1)%3]) ----
        if (t + 2 < 64)
            load_stage(sb + ((t + 2) % 3) * STAGE_BYTES, bblk, hblk, t + 2, tid);
    }

    // -------- store combined output --------
#pragma unroll
    for (int mt = 0; mt < 2; mt++) {
        int b0r = bblk * 128 + m0 + mt * 16 + grp;
#pragma unroll
        for (int ng = 0; ng < 4; ng++) {
            int h = hblk * 64 + n0 + ng * 8 + tig * 2;
            *(float2*)(out + (size_t)b0r * HID + h)       = make_float2(o[mt][ng][0], o[mt][ng][1]);
            *(float2*)(out + (size_t)(b0r + 8) * HID + h) = make_float2(o[mt][ng][2], o[mt][ng][3]);
        }
    }
}

// ---------------- launch ------------------------------------------------------
extern "C" void kernel_launch(void* const* d_in, const int* in_sizes, int n_in,
                              void* d_out, int out_size)
{
    const float* x   = (const float*)d_in[0];
    const float* gs  = (const float*)d_in[1];
    const void*  ei  = d_in[2];
    const float* ew  = (const float*)d_in[3];
    const float* eb  = (const float*)d_in[4];
    const float* bnw = (const float*)d_in[5];
    const float* bnb = (const float*)d_in[6];
    const float* rm  = (const float*)d_in[7];
    const float* rv  = (const float*)d_in[8];
    const float* gw  = (const float*)d_in[9];
    const float* lA  = (const float*)d_in[10];
    const float* lB  = (const float*)d_in[11];
    float* out = (float*)d_out;

    cudaFuncSetAttribute(fused_moe, cudaFuncAttributeMaxDynamicSharedMemorySize, SMEM_TOTAL);

    prep_W<<<(NEXP * IN_DIM * HID) / (256 * 16), 256>>>(ei, ew);
    prep_small<<<320, 256>>>(x, gs, gw, lA, lB, ei, eb, bnw, bnb, rm, rv);
    fused_moe<<<dim3(HID / 64, BATCH / 128), 256, SMEM_TOTAL>>>(out);
}